// round 1
// baseline (speedup 1.0000x reference)
#include <cuda_runtime.h>

// Device-global scratch for the 4x4 doubly-stochastic matrix H.
__device__ float g_H[16];

// ---------------------------------------------------------------------------
// Kernel 1: Sinkhorn normalization of the 4x4 H_raw. Single thread — 16
// floats, 20 iterations of row-normalize then col-normalize. Cost ~ a few us
// of launch overhead; arithmetically trivial.
// ---------------------------------------------------------------------------
__global__ void sinkhorn_kernel(const float* __restrict__ H_raw) {
    float A[4][4];
    #pragma unroll
    for (int i = 0; i < 4; i++)
        #pragma unroll
        for (int j = 0; j < 4; j++)
            A[i][j] = fabsf(H_raw[i * 4 + j]) + 1e-8f;

    for (int it = 0; it < 20; it++) {
        // Row normalize: A[i][j] /= sum_j A[i][j]
        #pragma unroll
        for (int i = 0; i < 4; i++) {
            float s = A[i][0] + A[i][1] + A[i][2] + A[i][3];
            float inv = 1.0f / s;
            #pragma unroll
            for (int j = 0; j < 4; j++) A[i][j] *= inv;
        }
        // Col normalize: A[i][j] /= sum_i A[i][j]
        #pragma unroll
        for (int j = 0; j < 4; j++) {
            float s = A[0][j] + A[1][j] + A[2][j] + A[3][j];
            float inv = 1.0f / s;
            #pragma unroll
            for (int i = 0; i < 4; i++) A[i][j] *= inv;
        }
    }

    #pragma unroll
    for (int i = 0; i < 4; i++)
        #pragma unroll
        for (int j = 0; j < 4; j++)
            g_H[i * 4 + j] = A[i][j];
}

// ---------------------------------------------------------------------------
// Kernel 2: stream mixing. out[bt, n, d] = sum_m H[n,m] * x[bt, m, d]
// x viewed as [BT=16384][M=4][DV=256 float4]. One thread per (bt, float4 of d):
//   4 float4 loads (one per input stream, 4KB apart -> per-warp fully
//   coalesced 128B transactions), 16 FMAs x 4 lanes, 4 float4 stores.
// Pure HBM streaming: 512 MB total traffic.
// ---------------------------------------------------------------------------
__global__ __launch_bounds__(256) void mix_kernel(const float4* __restrict__ x,
                                                  float4* __restrict__ out) {
    // gridDim.x = BT (16384), blockDim.x = 256 -> one block per bt,
    // thread q owns float4 index q of the 1024-float d dimension.
    const int bt = blockIdx.x;
    const int q  = threadIdx.x;

    const float4* __restrict__ xb = x + (size_t)bt * 1024;  // 4 streams * 256 float4
    float4* __restrict__ ob       = out + (size_t)bt * 1024;

    // Front-batch the 4 stream loads (MLP=4).
    float4 v0 = xb[0 * 256 + q];
    float4 v1 = xb[1 * 256 + q];
    float4 v2 = xb[2 * 256 + q];
    float4 v3 = xb[3 * 256 + q];

    // H broadcast-loads: all threads read the same 16 floats -> L1 broadcast.
    float h[16];
    #pragma unroll
    for (int i = 0; i < 16; i++) h[i] = __ldg(&g_H[i]);

    #pragma unroll
    for (int n = 0; n < 4; n++) {
        const float h0 = h[n * 4 + 0], h1 = h[n * 4 + 1];
        const float h2 = h[n * 4 + 2], h3 = h[n * 4 + 3];
        float4 o;
        o.x = h0 * v0.x + h1 * v1.x + h2 * v2.x + h3 * v3.x;
        o.y = h0 * v0.y + h1 * v1.y + h2 * v2.y + h3 * v3.y;
        o.z = h0 * v0.z + h1 * v1.z + h2 * v2.z + h3 * v3.z;
        o.w = h0 * v0.w + h1 * v1.w + h2 * v2.w + h3 * v3.w;
        ob[n * 256 + q] = o;
    }
}

extern "C" void kernel_launch(void* const* d_in, const int* in_sizes, int n_in,
                              void* d_out, int out_size) {
    const float* x     = (const float*)d_in[0];  // [4, 4096, 4, 1024] fp32
    const float* H_raw = (const float*)d_in[1];  // [4, 4]
    float* out         = (float*)d_out;          // [4, 4096, 4, 1024] fp32

    sinkhorn_kernel<<<1, 1>>>(H_raw);

    const int BT = 4 * 4096;  // 16384 (b,t) pairs
    mix_kernel<<<BT, 256>>>((const float4*)x, (float4*)out);
    (void)in_sizes; (void)n_in; (void)out_size;
}

// round 2
// speedup vs baseline: 1.0472x; 1.0472x over previous
#include <cuda_runtime.h>

// Device-global scratch for the 4x4 doubly-stochastic matrix H.
__device__ float g_H[16];

// ---------------------------------------------------------------------------
// Kernel 1: warp-parallel Sinkhorn on the 4x4 H_raw.
// Lane l (l<16) owns element (i=l/4, j=l%4). Row sums via shfl_xor within
// width-4 groups; col sums via shfl_xor {4,8} within width 16. Serial chain
// ~150 cyc/iter x 20 iters ~= 2us instead of ~10us single-thread.
// ---------------------------------------------------------------------------
__global__ void sinkhorn_kernel(const float* __restrict__ H_raw) {
    const int l = threadIdx.x;           // 32 threads, lanes >=16 compute junk
    const int e = l & 15;                // element index 0..15
    float a = fabsf(H_raw[e]) + 1e-8f;   // lanes 16..31 load duplicates (harmless)

    #pragma unroll 1
    for (int it = 0; it < 20; it++) {
        // Row normalize: sum over j (lanes within width-4 group)
        float s = a;
        s += __shfl_xor_sync(0xFFFFFFFFu, s, 1, 4);
        s += __shfl_xor_sync(0xFFFFFFFFu, s, 2, 4);
        a *= __frcp_rn(s);
        // Col normalize: same j across i -> lanes differing by 4, 8 (width 16)
        float c = a;
        c += __shfl_xor_sync(0xFFFFFFFFu, c, 4, 16);
        c += __shfl_xor_sync(0xFFFFFFFFu, c, 8, 16);
        a *= __frcp_rn(c);
    }

    if (l < 16) g_H[l] = a;
}

// ---------------------------------------------------------------------------
// Kernel 2: stream mixing. out[bt, n, d] = sum_m H[n,m] * x[bt, m, d]
// Each block handles TWO bt rows; thread q owns float4 lane q of d for both.
// 8 front-batched float4 loads (MLP=8), streaming cache hints (data is
// read-once / write-once). Pure HBM streaming: 512 MB total traffic.
// ---------------------------------------------------------------------------
__global__ __launch_bounds__(256) void mix_kernel(const float4* __restrict__ x,
                                                  float4* __restrict__ out) {
    const int bt0 = blockIdx.x * 2;
    const int q   = threadIdx.x;

    const float4* __restrict__ xa = x + (size_t)bt0 * 1024;        // bt0
    const float4* __restrict__ xb = xa + 1024;                      // bt0+1
    float4* __restrict__ oa       = out + (size_t)bt0 * 1024;
    float4* __restrict__ ob       = oa + 1024;

    // Front-batch all 8 stream loads (MLP=8), streaming (evict-first).
    float4 a0 = __ldcs(xa + 0 * 256 + q);
    float4 a1 = __ldcs(xa + 1 * 256 + q);
    float4 a2 = __ldcs(xa + 2 * 256 + q);
    float4 a3 = __ldcs(xa + 3 * 256 + q);
    float4 b0 = __ldcs(xb + 0 * 256 + q);
    float4 b1 = __ldcs(xb + 1 * 256 + q);
    float4 b2 = __ldcs(xb + 2 * 256 + q);
    float4 b3 = __ldcs(xb + 3 * 256 + q);

    // H broadcast-loads: all threads read the same 16 floats -> L1 broadcast.
    float h[16];
    #pragma unroll
    for (int i = 0; i < 16; i++) h[i] = __ldg(&g_H[i]);

    #pragma unroll
    for (int n = 0; n < 4; n++) {
        const float h0 = h[n * 4 + 0], h1 = h[n * 4 + 1];
        const float h2 = h[n * 4 + 2], h3 = h[n * 4 + 3];
        float4 o;
        o.x = h0 * a0.x + h1 * a1.x + h2 * a2.x + h3 * a3.x;
        o.y = h0 * a0.y + h1 * a1.y + h2 * a2.y + h3 * a3.y;
        o.z = h0 * a0.z + h1 * a1.z + h2 * a2.z + h3 * a3.z;
        o.w = h0 * a0.w + h1 * a1.w + h2 * a2.w + h3 * a3.w;
        __stcs(oa + n * 256 + q, o);
    }
    #pragma unroll
    for (int n = 0; n < 4; n++) {
        const float h0 = h[n * 4 + 0], h1 = h[n * 4 + 1];
        const float h2 = h[n * 4 + 2], h3 = h[n * 4 + 3];
        float4 o;
        o.x = h0 * b0.x + h1 * b1.x + h2 * b2.x + h3 * b3.x;
        o.y = h0 * b0.y + h1 * b1.y + h2 * b2.y + h3 * b3.y;
        o.z = h0 * b0.z + h1 * b1.z + h2 * b2.z + h3 * b3.z;
        o.w = h0 * b0.w + h1 * b1.w + h2 * b2.w + h3 * b3.w;
        __stcs(ob + n * 256 + q, o);
    }
}

extern "C" void kernel_launch(void* const* d_in, const int* in_sizes, int n_in,
                              void* d_out, int out_size) {
    const float* x     = (const float*)d_in[0];  // [4, 4096, 4, 1024] fp32
    const float* H_raw = (const float*)d_in[1];  // [4, 4]
    float* out         = (float*)d_out;          // [4, 4096, 4, 1024] fp32

    sinkhorn_kernel<<<1, 32>>>(H_raw);

    const int BT = 4 * 4096;  // 16384 (b,t) pairs, 2 per block
    mix_kernel<<<BT / 2, 256>>>((const float4*)x, (float4*)out);
    (void)in_sizes; (void)n_in; (void)out_size;
}